// round 1
// baseline (speedup 1.0000x reference)
#include <cuda_runtime.h>
#include <math.h>

// Problem constants (fixed shapes per reference setup_inputs)
#define B_    4
#define L_    4096
#define D_    1024
#define DFF_  4096
#define KCAP_ 2048   // int(L * 0.5)

// ---------------- scratch (no allocations allowed) ----------------
__device__ float g_scores[B_ * L_];
__device__ int   g_flags[B_ * L_];
__device__ int   g_selidx[B_ * KCAP_];
__device__ float g_h[(size_t)B_ * KCAP_ * DFF_];   // 128 MiB FFN hidden

// ---------------- router scores: one warp per token ----------------
__global__ void router_scores_kernel(const float* __restrict__ x,
                                     const float* __restrict__ wr) {
    int gwarp = (blockIdx.x * blockDim.x + threadIdx.x) >> 5;
    int lane  = threadIdx.x & 31;
    if (gwarp >= B_ * L_) return;
    const float4* xr = (const float4*)(x + (size_t)gwarp * D_);
    const float4* w4 = (const float4*)wr;
    float acc = 0.f;
#pragma unroll
    for (int i = 0; i < D_ / 4 / 32; i++) {
        float4 a = xr[lane + i * 32];
        float4 b = w4[lane + i * 32];
        acc += a.x * b.x + a.y * b.y + a.z * b.z + a.w * b.w;
    }
#pragma unroll
    for (int off = 16; off; off >>= 1)
        acc += __shfl_xor_sync(0xffffffffu, acc, off);
    if (lane == 0) g_scores[gwarp] = acc;
}

// ---------------- rank-based top-k flags -------------------------
// grid: (L/1024, B), block 1024. rank(l) < k  <=>  l in stable top-k.
__global__ void rank_kernel() {
    __shared__ float s[L_];
    int b = blockIdx.y;
    int t = threadIdx.x;
    const float* sc = g_scores + b * L_;
    for (int i = t; i < L_; i += 1024) s[i] = sc[i];
    __syncthreads();
    int   l  = blockIdx.x * 1024 + t;
    float sl = s[l];
    int rank = 0;
#pragma unroll 8
    for (int j = 0; j < L_; j++) {
        float sj = s[j];
        rank += (sj > sl) || (sj == sl && j < l);
    }
    g_flags[b * L_ + l] = (rank < KCAP_) ? 1 : 0;
}

// ---------------- compact flags -> sorted selected indices --------
// grid: B, block 1024, each thread owns 4 contiguous tokens
__global__ void compact_kernel() {
    int b = blockIdx.x;
    int t = threadIdx.x;
    int tok0 = t * 4;
    int f[4], c = 0;
#pragma unroll
    for (int i = 0; i < 4; i++) {
        f[i] = g_flags[b * L_ + tok0 + i];
        c += f[i];
    }
    int lane = t & 31, w = t >> 5;
    int inc = c;
#pragma unroll
    for (int off = 1; off < 32; off <<= 1) {
        int y = __shfl_up_sync(0xffffffffu, inc, off);
        if (lane >= off) inc += y;
    }
    __shared__ int ws[32];
    if (lane == 31) ws[w] = inc;
    __syncthreads();
    if (w == 0) {
        int v = ws[lane];
#pragma unroll
        for (int off = 1; off < 32; off <<= 1) {
            int y = __shfl_up_sync(0xffffffffu, v, off);
            if (lane >= off) v += y;
        }
        ws[lane] = v;
    }
    __syncthreads();
    int base = inc - c + (w ? ws[w - 1] : 0);
#pragma unroll
    for (int i = 0; i < 4; i++) {
        if (f[i]) {
            g_selidx[b * KCAP_ + base] = tok0 + i;
            base++;
        }
    }
}

// ---------------- GELU (jax default: tanh approximation) ----------
__device__ __forceinline__ float gelu_tanh(float v) {
    const float c = 0.7978845608028654f;   // sqrt(2/pi)
    float u = c * (v + 0.044715f * v * v * v);
    return 0.5f * v * (1.0f + tanhf(u));
}

// ---------------- NT SGEMM: C[m,n] = sum_k A[m,k]*Bw[n,k] ---------
// 128x128x16 tiles, 256 threads, 8x8 per thread.
// A_IS_H / C_IS_H: use g_h device global instead of the passed pointer.
// GATHER_A: A row m reads x row (m>>11)*L + selidx[m]  (FFN input gather)
// SCATTER_C: C row m writes out row (m>>11)*L + selidx[m] (overwrite bypass)
template <bool A_IS_H, bool C_IS_H, bool GATHER_A, bool SCATTER_C, bool GELU>
__global__ void __launch_bounds__(256, 2)
sgemm_nt(const float* __restrict__ A_in, const float* __restrict__ Bw,
         float* __restrict__ C_in, int M, int N, int K) {
    __shared__ float As[16][132];
    __shared__ float Bs[16][132];

    const float* A = A_IS_H ? (const float*)g_h : A_in;
    float*       C = C_IS_H ? (float*)g_h : C_in;

    int tid = threadIdx.x;
    int bm = blockIdx.y, bn = blockIdx.x;

    // global-load addressing: 2 rows of A, 2 rows of B per thread (float4)
    int lr  = tid >> 2;            // 0..63
    int ag  = (tid & 3) * 4;       // k offset within 16
    int ar0 = bm * 128 + lr;
    int ar1 = ar0 + 64;

    const float* Ap0;
    const float* Ap1;
    if (GATHER_A) {
        Ap0 = A + ((size_t)((ar0 >> 11) * L_ + g_selidx[ar0])) * K;
        Ap1 = A + ((size_t)((ar1 >> 11) * L_ + g_selidx[ar1])) * K;
    } else {
        Ap0 = A + (size_t)ar0 * K;
        Ap1 = A + (size_t)ar1 * K;
    }
    int br0 = bn * 128 + lr;
    int br1 = br0 + 64;
    const float* Bp0 = Bw + (size_t)br0 * K;
    const float* Bp1 = Bw + (size_t)br1 * K;

    float acc[8][8];
#pragma unroll
    for (int i = 0; i < 8; i++)
#pragma unroll
        for (int j = 0; j < 8; j++) acc[i][j] = 0.f;

    int trow = tid >> 4, tcol = tid & 15;  // 16x16 thread grid
    int rm = trow * 4;
    int cn = tcol * 4;

    for (int k0 = 0; k0 < K; k0 += 16) {
        float4 a0 = *(const float4*)(Ap0 + k0 + ag);
        float4 a1 = *(const float4*)(Ap1 + k0 + ag);
        float4 b0 = *(const float4*)(Bp0 + k0 + ag);
        float4 b1 = *(const float4*)(Bp1 + k0 + ag);
        __syncthreads();   // previous tile's smem reads done
        As[ag + 0][lr] = a0.x; As[ag + 1][lr] = a0.y;
        As[ag + 2][lr] = a0.z; As[ag + 3][lr] = a0.w;
        As[ag + 0][lr + 64] = a1.x; As[ag + 1][lr + 64] = a1.y;
        As[ag + 2][lr + 64] = a1.z; As[ag + 3][lr + 64] = a1.w;
        Bs[ag + 0][lr] = b0.x; Bs[ag + 1][lr] = b0.y;
        Bs[ag + 2][lr] = b0.z; Bs[ag + 3][lr] = b0.w;
        Bs[ag + 0][lr + 64] = b1.x; Bs[ag + 1][lr + 64] = b1.y;
        Bs[ag + 2][lr + 64] = b1.z; Bs[ag + 3][lr + 64] = b1.w;
        __syncthreads();

#pragma unroll
        for (int kk = 0; kk < 16; kk++) {
            float a[8], bb[8];
            *(float4*)&a[0]  = *(const float4*)&As[kk][rm];
            *(float4*)&a[4]  = *(const float4*)&As[kk][rm + 64];
            *(float4*)&bb[0] = *(const float4*)&Bs[kk][cn];
            *(float4*)&bb[4] = *(const float4*)&Bs[kk][cn + 64];
#pragma unroll
            for (int i = 0; i < 8; i++)
#pragma unroll
                for (int j = 0; j < 8; j++)
                    acc[i][j] = fmaf(a[i], bb[j], acc[i][j]);
        }
    }

    // epilogue
#pragma unroll
    for (int i = 0; i < 8; i++) {
        int r = bm * 128 + rm + ((i < 4) ? i : (64 + i - 4));
        int gr;
        if (SCATTER_C) gr = (r >> 11) * L_ + g_selidx[r];
        else           gr = r;
        float* Cp = C + (size_t)gr * N + bn * 128;
        float v[8];
#pragma unroll
        for (int j = 0; j < 8; j++) {
            float val = acc[i][j];
            if (GELU) val = gelu_tanh(val);
            v[j] = val;
        }
        *(float4*)(Cp + cn)      = *(float4*)&v[0];
        *(float4*)(Cp + cn + 64) = *(float4*)&v[4];
    }
}

// ---------------- launch ------------------------------------------
extern "C" void kernel_launch(void* const* d_in, const int* in_sizes, int n_in,
                              void* d_out, int out_size) {
    const float* x  = (const float*)d_in[0];  // (B,L,D)
    const float* wr = (const float*)d_in[1];  // (D,)
    const float* wb = (const float*)d_in[2];  // (D,D)
    const float* w1 = (const float*)d_in[3];  // (Dff,D)
    const float* w2 = (const float*)d_in[4];  // (D,Dff)
    float* out = (float*)d_out;               // (B,L,D)

    // 1) router scores: 8 warps/block
    router_scores_kernel<<<(B_ * L_) / 8, 256>>>(x, wr);

    // 2) top-k selection flags (rank < k)
    rank_kernel<<<dim3(L_ / 1024, B_), 1024>>>();

    // 3) compact to sorted selected indices
    compact_kernel<<<B_, 1024>>>();

    // 4) bypass: out = x @ wb^T  (all tokens)   M=B*L, N=D, K=D
    sgemm_nt<false, false, false, false, false>
        <<<dim3(D_ / 128, (B_ * L_) / 128), 256>>>(x, wb, out, B_ * L_, D_, D_);

    // 5) FFN layer 1 (gather selected rows of x, GELU): h = gelu(x_sel @ w1^T)
    //    M=B*k, N=Dff, K=D
    sgemm_nt<false, true, true, false, true>
        <<<dim3(DFF_ / 128, (B_ * KCAP_) / 128), 256>>>(x, w1, nullptr,
                                                        B_ * KCAP_, DFF_, D_);

    // 6) FFN layer 2 (scatter-overwrite into out): out[sel] = h @ w2^T
    //    M=B*k, N=D, K=Dff
    sgemm_nt<true, false, false, true, false>
        <<<dim3(D_ / 128, (B_ * KCAP_) / 128), 256>>>(nullptr, w2, out,
                                                      B_ * KCAP_, D_, DFF_);
}

// round 3
// speedup vs baseline: 2.3909x; 2.3909x over previous
#include <cuda_runtime.h>
#include <cuda_bf16.h>
#include <math.h>
#include <stdint.h>

#define B_    4
#define L_    4096
#define D_    1024
#define DFF_  4096
#define KCAP_ 2048
#define UNSEL_ 2048   // L - k

// ------------------------- scratch globals (no allocs) -------------------------
__device__ float g_scores[B_ * L_];
__device__ int   g_flags[B_ * L_];
__device__ int   g_selidx[B_ * KCAP_];
__device__ int   g_unselidx[B_ * UNSEL_];

__device__ __align__(16) __nv_bfloat16 g_xgh[(size_t)B_ * KCAP_ * D_];
__device__ __align__(16) __nv_bfloat16 g_xgl[(size_t)B_ * KCAP_ * D_];
__device__ __align__(16) __nv_bfloat16 g_xuh[(size_t)B_ * UNSEL_ * D_];
__device__ __align__(16) __nv_bfloat16 g_xul[(size_t)B_ * UNSEL_ * D_];
__device__ __align__(16) __nv_bfloat16 g_wbh[(size_t)D_ * D_];
__device__ __align__(16) __nv_bfloat16 g_wbl[(size_t)D_ * D_];
__device__ __align__(16) __nv_bfloat16 g_w1h[(size_t)DFF_ * D_];
__device__ __align__(16) __nv_bfloat16 g_w1l[(size_t)DFF_ * D_];
__device__ __align__(16) __nv_bfloat16 g_w2h[(size_t)D_ * DFF_];
__device__ __align__(16) __nv_bfloat16 g_w2l[(size_t)D_ * DFF_];
__device__ __align__(16) __nv_bfloat16 g_hh [(size_t)B_ * KCAP_ * DFF_];
__device__ __align__(16) __nv_bfloat16 g_hl [(size_t)B_ * KCAP_ * DFF_];

// ------------------------- helpers -------------------------
__device__ __forceinline__ uint32_t smem_u32(const void* p) {
    uint32_t a;
    asm("{ .reg .u64 t; cvta.to.shared.u64 t, %1; cvt.u32.u64 %0, t; }"
        : "=r"(a) : "l"(p));
    return a;
}
__device__ __forceinline__ void cp16(uint32_t dst, const void* src) {
    asm volatile("cp.async.cg.shared.global [%0], [%1], 16;" :: "r"(dst), "l"(src));
}
#define CP_COMMIT() asm volatile("cp.async.commit_group;" ::: "memory")
#define CP_WAIT1()  asm volatile("cp.async.wait_group 1;" ::: "memory")

__device__ __forceinline__ void ldx4(uint32_t r[4], uint32_t addr) {
    asm volatile("ldmatrix.sync.aligned.m8n8.x4.shared.b16 {%0,%1,%2,%3}, [%4];"
                 : "=r"(r[0]), "=r"(r[1]), "=r"(r[2]), "=r"(r[3]) : "r"(addr));
}
__device__ __forceinline__ void mma16816(float c[4], const uint32_t a[4], const uint32_t b[2]) {
    asm volatile(
        "mma.sync.aligned.m16n8k16.row.col.f32.bf16.bf16.f32 "
        "{%0,%1,%2,%3}, {%4,%5,%6,%7}, {%8,%9}, {%0,%1,%2,%3};"
        : "+f"(c[0]), "+f"(c[1]), "+f"(c[2]), "+f"(c[3])
        : "r"(a[0]), "r"(a[1]), "r"(a[2]), "r"(a[3]), "r"(b[0]), "r"(b[1]));
}

__device__ __forceinline__ void split_bf16(float v, unsigned short& h, unsigned short& l) {
    __nv_bfloat16 hb = __float2bfloat16(v);
    __nv_bfloat16 lb = __float2bfloat16(v - __bfloat162float(hb));
    h = __bfloat16_as_ushort(hb);
    l = __bfloat16_as_ushort(lb);
}
__device__ __forceinline__ float gelu_tanh(float v) {
    const float c = 0.7978845608028654f;
    float u = c * (v + 0.044715f * v * v * v);
    return 0.5f * v * (1.0f + tanhf(u));
}

// ------------------------- router / top-k / compact -------------------------
__global__ void router_scores_kernel(const float* __restrict__ x,
                                     const float* __restrict__ wr) {
    int gwarp = (blockIdx.x * blockDim.x + threadIdx.x) >> 5;
    int lane  = threadIdx.x & 31;
    if (gwarp >= B_ * L_) return;
    const float4* xr = (const float4*)(x + (size_t)gwarp * D_);
    const float4* w4 = (const float4*)wr;
    float acc = 0.f;
#pragma unroll
    for (int i = 0; i < D_ / 4 / 32; i++) {
        float4 a = xr[lane + i * 32];
        float4 b = w4[lane + i * 32];
        acc += a.x * b.x + a.y * b.y + a.z * b.z + a.w * b.w;
    }
#pragma unroll
    for (int off = 16; off; off >>= 1)
        acc += __shfl_xor_sync(0xffffffffu, acc, off);
    if (lane == 0) g_scores[gwarp] = acc;
}

__global__ void rank_kernel() {
    __shared__ float s[L_];
    int b = blockIdx.y;
    int t = threadIdx.x;
    const float* sc = g_scores + b * L_;
    for (int i = t; i < L_; i += 1024) s[i] = sc[i];
    __syncthreads();
    int   l  = blockIdx.x * 1024 + t;
    float sl = s[l];
    int rank = 0;
#pragma unroll 8
    for (int j = 0; j < L_; j++) {
        float sj = s[j];
        rank += (sj > sl) || (sj == sl && j < l);
    }
    g_flags[b * L_ + l] = (rank < KCAP_) ? 1 : 0;
}

__global__ void compact_kernel() {
    int b = blockIdx.x;
    int t = threadIdx.x;
    int tok0 = t * 4;
    int f[4], c = 0;
#pragma unroll
    for (int i = 0; i < 4; i++) {
        f[i] = g_flags[b * L_ + tok0 + i];
        c += f[i];
    }
    int lane = t & 31, w = t >> 5;
    int inc = c;
#pragma unroll
    for (int off = 1; off < 32; off <<= 1) {
        int y = __shfl_up_sync(0xffffffffu, inc, off);
        if (lane >= off) inc += y;
    }
    __shared__ int ws[32];
    if (lane == 31) ws[w] = inc;
    __syncthreads();
    if (w == 0) {
        int v = ws[lane];
#pragma unroll
        for (int off = 1; off < 32; off <<= 1) {
            int y = __shfl_up_sync(0xffffffffu, v, off);
            if (lane >= off) v += y;
        }
        ws[lane] = v;
    }
    __syncthreads();
    int selp = inc - c + (w ? ws[w - 1] : 0);     // exclusive prefix of selected
    int unsp = tok0 - selp;                       // exclusive prefix of unselected
#pragma unroll
    for (int i = 0; i < 4; i++) {
        if (f[i]) g_selidx[b * KCAP_ + selp++] = tok0 + i;
        else      g_unselidx[b * UNSEL_ + unsp++] = tok0 + i;
    }
}

// ------------------------- conversions -------------------------
__global__ void convert_split_kernel(const float* __restrict__ src,
                                     __nv_bfloat16* __restrict__ hi,
                                     __nv_bfloat16* __restrict__ lo, int n4) {
    int i = blockIdx.x * blockDim.x + threadIdx.x;
    if (i >= n4) return;
    float4 v = ((const float4*)src)[i];
    unsigned short h0, h1, h2, h3, l0, l1, l2, l3;
    split_bf16(v.x, h0, l0); split_bf16(v.y, h1, l1);
    split_bf16(v.z, h2, l2); split_bf16(v.w, h3, l3);
    ((ushort4*)hi)[i] = make_ushort4(h0, h1, h2, h3);
    ((ushort4*)lo)[i] = make_ushort4(l0, l1, l2, l3);
}

__global__ void gather_convert_kernel(const float* __restrict__ x,
                                      const int* __restrict__ idx,
                                      __nv_bfloat16* __restrict__ hi,
                                      __nv_bfloat16* __restrict__ lo) {
    int i = blockIdx.x * blockDim.x + threadIdx.x;   // rows*256 threads
    int r = i >> 8;
    int c4 = i & 255;
    int srow = (r >> 11) * L_ + idx[r];
    float4 v = ((const float4*)(x + (size_t)srow * D_))[c4];
    unsigned short h0, h1, h2, h3, l0, l1, l2, l3;
    split_bf16(v.x, h0, l0); split_bf16(v.y, h1, l1);
    split_bf16(v.z, h2, l2); split_bf16(v.w, h3, l3);
    ((ushort4*)hi)[i] = make_ushort4(h0, h1, h2, h3);
    ((ushort4*)lo)[i] = make_ushort4(l0, l1, l2, l3);
}

// ------------------------- HMMA GEMM (bf16 split-3) -------------------------
// C[m,n] = sum_k A[m,k]*B[n,k]   with A = Ah+Al, B = Bh+Bl (drop Al*Bl)
// WHICH 0: bypass  A=g_xu*, B=wb, C scatter->out via unselidx   M=8192 N=1024 K=1024
// WHICH 1: ffn1    A=g_xg*, B=w1, C=gelu->split->g_hh/g_hl      M=8192 N=4096 K=1024
// WHICH 2: ffn2    A=g_h*,  B=w2, C scatter->out via selidx     M=8192 N=1024 K=4096
#define BKC     32
#define ROWB    80                 // 32 bf16 = 64B, padded to 80B
#define TILEB   (128 * ROWB)       // 10240
#define STAGEB  (4 * TILEB)        // 40960
#define NSTAGE  3
#define SMEMB   (NSTAGE * STAGEB)  // 122880

template <int WHICH>
__global__ void __launch_bounds__(256, 1) gemm_mma(float* __restrict__ outp) {
    constexpr int N  = (WHICH == 1) ? DFF_ : D_;
    constexpr int K  = (WHICH == 2) ? DFF_ : D_;
    constexpr int NK = K / BKC;

    const __nv_bfloat16* Ah = (WHICH == 0) ? g_xuh : (WHICH == 1) ? g_xgh : g_hh;
    const __nv_bfloat16* Al = (WHICH == 0) ? g_xul : (WHICH == 1) ? g_xgl : g_hl;
    const __nv_bfloat16* Bh = (WHICH == 0) ? g_wbh : (WHICH == 1) ? g_w1h : g_w2h;
    const __nv_bfloat16* Bl = (WHICH == 0) ? g_wbl : (WHICH == 1) ? g_w1l : g_w2l;

    extern __shared__ char smem[];
    const uint32_t sbase = smem_u32(smem);

    const int tid  = threadIdx.x;
    const int lane = tid & 31;
    const int wid  = tid >> 5;
    const int bm = blockIdx.y, bn = blockIdx.x;

    // ---- cp.async source/dst precompute: 8 x 16B per thread per stage ----
    const int prow = tid >> 2;          // 0..63
    const int pcol = (tid & 3) * 8;     // element offset of 16B chunk
    const __nv_bfloat16* srcA0 = Ah + (size_t)(bm * 128 + prow) * K + pcol;
    const __nv_bfloat16* srcA1 = Ah + (size_t)(bm * 128 + prow + 64) * K + pcol;
    const __nv_bfloat16* srcL0 = Al + (size_t)(bm * 128 + prow) * K + pcol;
    const __nv_bfloat16* srcL1 = Al + (size_t)(bm * 128 + prow + 64) * K + pcol;
    const __nv_bfloat16* srcB0 = Bh + (size_t)(bn * 128 + prow) * K + pcol;
    const __nv_bfloat16* srcB1 = Bh + (size_t)(bn * 128 + prow + 64) * K + pcol;
    const __nv_bfloat16* srcC0 = Bl + (size_t)(bn * 128 + prow) * K + pcol;
    const __nv_bfloat16* srcC1 = Bl + (size_t)(bn * 128 + prow + 64) * K + pcol;
    const uint32_t dst0 = prow * ROWB + (tid & 3) * 16;
    const uint32_t dst1 = dst0 + 64 * ROWB;

#define LOAD_STAGE(ks, st) do {                                           \
        uint32_t b0 = sbase + (st) * STAGEB;                              \
        int ko = (ks) * BKC;                                              \
        cp16(b0 + dst0,              srcA0 + ko);                         \
        cp16(b0 + dst1,              srcA1 + ko);                         \
        cp16(b0 + TILEB + dst0,      srcL0 + ko);                         \
        cp16(b0 + TILEB + dst1,      srcL1 + ko);                         \
        cp16(b0 + 2 * TILEB + dst0,  srcB0 + ko);                         \
        cp16(b0 + 2 * TILEB + dst1,  srcB1 + ko);                         \
        cp16(b0 + 3 * TILEB + dst0,  srcC0 + ko);                         \
        cp16(b0 + 3 * TILEB + dst1,  srcC1 + ko);                         \
        CP_COMMIT();                                                      \
    } while (0)

    // ---- warp tiling: 2(m) x 4(n) warps, warp tile 64x32 ----
    const uint32_t wrow0 = (wid & 1) * 64;
    const uint32_t wcol0 = (wid >> 1) * 32;

    // ldmatrix lane addressing (A: [m][k] rows; B: [n][k] rows)
    const uint32_t aRow = wrow0 + (lane & 15);         // + i*16
    const uint32_t aK   = (lane >> 4);                 // k-half select
    const uint32_t bRow = wcol0 + ((lane >> 4) << 3) + (lane & 7);   // + jp*16
    const uint32_t bK   = (lane >> 3) & 1;

    float acc[4][4][4];
#pragma unroll
    for (int i = 0; i < 4; i++)
#pragma unroll
        for (int j = 0; j < 4; j++)
#pragma unroll
            for (int q = 0; q < 4; q++) acc[i][j][q] = 0.f;

    // prologue
    LOAD_STAGE(0, 0);
    LOAD_STAGE(1, 1);

    int st = 0;
    for (int ks = 0; ks < NK; ks++) {
        CP_WAIT1();
        __syncthreads();

        const uint32_t base = sbase + st * STAGEB;
#pragma unroll
        for (int s = 0; s < 2; s++) {
            uint32_t ah[4][4], al[4][4], bh[4][2], bl[4][2];
#pragma unroll
            for (int i = 0; i < 4; i++)
                ldx4(ah[i], base + (aRow + i * 16) * ROWB + (2 * s + aK) * 16);
#pragma unroll
            for (int jp = 0; jp < 2; jp++) {
                uint32_t r[4];
                ldx4(r, base + 2 * TILEB + (bRow + jp * 16) * ROWB + (2 * s + bK) * 16);
                bh[2 * jp][0] = r[0]; bh[2 * jp][1] = r[1];
                bh[2 * jp + 1][0] = r[2]; bh[2 * jp + 1][1] = r[3];
            }
#pragma unroll
            for (int i = 0; i < 4; i++)
#pragma unroll
                for (int j = 0; j < 4; j++) mma16816(acc[i][j], ah[i], bh[j]);

#pragma unroll
            for (int jp = 0; jp < 2; jp++) {
                uint32_t r[4];
                ldx4(r, base + 3 * TILEB + (bRow + jp * 16) * ROWB + (2 * s + bK) * 16);
                bl[2 * jp][0] = r[0]; bl[2 * jp][1] = r[1];
                bl[2 * jp + 1][0] = r[2]; bl[2 * jp + 1][1] = r[3];
            }
#pragma unroll
            for (int i = 0; i < 4; i++)
#pragma unroll
                for (int j = 0; j < 4; j++) mma16816(acc[i][j], ah[i], bl[j]);

#pragma unroll
            for (int i = 0; i < 4; i++)
                ldx4(al[i], base + TILEB + (aRow + i * 16) * ROWB + (2 * s + aK) * 16);
#pragma unroll
            for (int i = 0; i < 4; i++)
#pragma unroll
                for (int j = 0; j < 4; j++) mma16816(acc[i][j], al[i], bh[j]);
        }

        int nk2 = ks + NSTAGE - 1;
        if (nk2 < NK) {
            int st2 = st + (NSTAGE - 1); if (st2 >= NSTAGE) st2 -= NSTAGE;
            LOAD_STAGE(nk2, st2);
        } else {
            CP_COMMIT();
        }
        if (++st == NSTAGE) st = 0;
    }

    // ---- epilogue ----
    const int t4  = lane >> 2;
    const int tm2 = (lane & 3) * 2;
#pragma unroll
    for (int i = 0; i < 4; i++) {
        int r0 = bm * 128 + (int)wrow0 + i * 16 + t4;
        int r1 = r0 + 8;
        int or0, or1;
        if (WHICH == 0)      { or0 = (r0 >> 11) * L_ + g_unselidx[r0]; or1 = (r1 >> 11) * L_ + g_unselidx[r1]; }
        else if (WHICH == 2) { or0 = (r0 >> 11) * L_ + g_selidx[r0];   or1 = (r1 >> 11) * L_ + g_selidx[r1];   }
        else                 { or0 = r0; or1 = r1; }
#pragma unroll
        for (int j = 0; j < 4; j++) {
            int col = bn * 128 + (int)wcol0 + j * 8 + tm2;
            if (WHICH == 1) {
                float v00 = gelu_tanh(acc[i][j][0]);
                float v01 = gelu_tanh(acc[i][j][1]);
                float v10 = gelu_tanh(acc[i][j][2]);
                float v11 = gelu_tanh(acc[i][j][3]);
                unsigned short h00, h01, h10, h11, l00, l01, l10, l11;
                split_bf16(v00, h00, l00); split_bf16(v01, h01, l01);
                split_bf16(v10, h10, l10); split_bf16(v11, h11, l11);
                *(uint32_t*)(g_hh + (size_t)r0 * DFF_ + col) = (uint32_t)h00 | ((uint32_t)h01 << 16);
                *(uint32_t*)(g_hl + (size_t)r0 * DFF_ + col) = (uint32_t)l00 | ((uint32_t)l01 << 16);
                *(uint32_t*)(g_hh + (size_t)r1 * DFF_ + col) = (uint32_t)h10 | ((uint32_t)h11 << 16);
                *(uint32_t*)(g_hl + (size_t)r1 * DFF_ + col) = (uint32_t)l10 | ((uint32_t)l11 << 16);
            } else {
                *(float2*)(outp + (size_t)or0 * D_ + col) = make_float2(acc[i][j][0], acc[i][j][1]);
                *(float2*)(outp + (size_t)or1 * D_ + col) = make_float2(acc[i][j][2], acc[i][j][3]);
            }
        }
    }
    (void)N;
}

// ------------------------- launch -------------------------
extern "C" void kernel_launch(void* const* d_in, const int* in_sizes, int n_in,
                              void* d_out, int out_size) {
    const float* x  = (const float*)d_in[0];
    const float* wr = (const float*)d_in[1];
    const float* wb = (const float*)d_in[2];
    const float* w1 = (const float*)d_in[3];
    const float* w2 = (const float*)d_in[4];
    float* out = (float*)d_out;

    cudaFuncSetAttribute(gemm_mma<0>, cudaFuncAttributeMaxDynamicSharedMemorySize, SMEMB);
    cudaFuncSetAttribute(gemm_mma<1>, cudaFuncAttributeMaxDynamicSharedMemorySize, SMEMB);
    cudaFuncSetAttribute(gemm_mma<2>, cudaFuncAttributeMaxDynamicSharedMemorySize, SMEMB);

    // routing
    router_scores_kernel<<<(B_ * L_) / 8, 256>>>(x, wr);
    rank_kernel<<<dim3(L_ / 1024, B_), 1024>>>();
    compact_kernel<<<B_, 1024>>>();

    // symbol addresses for conversion kernels
    __nv_bfloat16 *p_wbh, *p_wbl, *p_w1h, *p_w1l, *p_w2h, *p_w2l;
    __nv_bfloat16 *p_xgh, *p_xgl, *p_xuh, *p_xul;
    int *p_sel, *p_unsel;
    cudaGetSymbolAddress((void**)&p_wbh, g_wbh);
    cudaGetSymbolAddress((void**)&p_wbl, g_wbl);
    cudaGetSymbolAddress((void**)&p_w1h, g_w1h);
    cudaGetSymbolAddress((void**)&p_w1l, g_w1l);
    cudaGetSymbolAddress((void**)&p_w2h, g_w2h);
    cudaGetSymbolAddress((void**)&p_w2l, g_w2l);
    cudaGetSymbolAddress((void**)&p_xgh, g_xgh);
    cudaGetSymbolAddress((void**)&p_xgl, g_xgl);
    cudaGetSymbolAddress((void**)&p_xuh, g_xuh);
    cudaGetSymbolAddress((void**)&p_xul, g_xul);
    cudaGetSymbolAddress((void**)&p_sel, g_selidx);
    cudaGetSymbolAddress((void**)&p_unsel, g_unselidx);

    convert_split_kernel<<<(D_ * D_ / 4) / 256, 256>>>(wb, p_wbh, p_wbl, D_ * D_ / 4);
    convert_split_kernel<<<(DFF_ * D_ / 4) / 256, 256>>>(w1, p_w1h, p_w1l, DFF_ * D_ / 4);
    convert_split_kernel<<<(D_ * DFF_ / 4) / 256, 256>>>(w2, p_w2h, p_w2l, D_ * DFF_ / 4);
    gather_convert_kernel<<<(B_ * KCAP_  * 256) / 256, 256>>>(x, p_sel,   p_xgh, p_xgl);
    gather_convert_kernel<<<(B_ * UNSEL_ * 256) / 256, 256>>>(x, p_unsel, p_xuh, p_xul);

    // GEMMs (M=8192 each -> grid.y = 64)
    gemm_mma<0><<<dim3(D_ / 128,   64), 256, SMEMB>>>(out);   // bypass (unselected only)
    gemm_mma<1><<<dim3(DFF_ / 128, 64), 256, SMEMB>>>(out);   // ffn1 + gelu + split
    gemm_mma<2><<<dim3(D_ / 128,   64), 256, SMEMB>>>(out);   // ffn2 scatter
}

// round 4
// speedup vs baseline: 3.0793x; 1.2879x over previous
#include <cuda_runtime.h>
#include <cuda_bf16.h>
#include <cuda_fp16.h>
#include <math.h>
#include <stdint.h>

#define B_    4
#define L_    4096
#define D_    1024
#define DFF_  4096
#define KCAP_ 2048
#define UNSEL_ 2048

// ------------------------- scratch globals -------------------------
__device__ float g_scores[B_ * L_];
__device__ int   g_flags[B_ * L_];
__device__ int   g_selidx[B_ * KCAP_];
__device__ int   g_unselidx[B_ * UNSEL_];

__device__ __align__(16) __half g_xg16[(size_t)B_ * KCAP_ * D_];
__device__ __align__(16) __half g_xu16[(size_t)B_ * UNSEL_ * D_];
__device__ __align__(16) __half g_wbh[(size_t)D_ * D_];
__device__ __align__(16) __half g_wbl[(size_t)D_ * D_];
__device__ __align__(16) __half g_w1h[(size_t)DFF_ * D_];
__device__ __align__(16) __half g_w1l[(size_t)DFF_ * D_];
__device__ __align__(16) __half g_w2h[(size_t)D_ * DFF_];
__device__ __align__(16) __half g_w2l[(size_t)D_ * DFF_];
__device__ __align__(16) __half g_h16[(size_t)B_ * KCAP_ * DFF_];

// ------------------------- helpers -------------------------
__device__ __forceinline__ uint32_t smem_u32(const void* p) {
    uint32_t a;
    asm("{ .reg .u64 t; cvta.to.shared.u64 t, %1; cvt.u32.u64 %0, t; }"
        : "=r"(a) : "l"(p));
    return a;
}
__device__ __forceinline__ void cp16(uint32_t dst, const void* src) {
    asm volatile("cp.async.cg.shared.global [%0], [%1], 16;" :: "r"(dst), "l"(src));
}
#define CP_COMMIT() asm volatile("cp.async.commit_group;" ::: "memory")
#define CP_WAIT2()  asm volatile("cp.async.wait_group 2;" ::: "memory")

__device__ __forceinline__ void ldx4(uint32_t r[4], uint32_t addr) {
    asm volatile("ldmatrix.sync.aligned.m8n8.x4.shared.b16 {%0,%1,%2,%3}, [%4];"
                 : "=r"(r[0]), "=r"(r[1]), "=r"(r[2]), "=r"(r[3]) : "r"(addr));
}
__device__ __forceinline__ void mma16816(float c[4], const uint32_t a[4], const uint32_t b[2]) {
    asm volatile(
        "mma.sync.aligned.m16n8k16.row.col.f32.f16.f16.f32 "
        "{%0,%1,%2,%3}, {%4,%5,%6,%7}, {%8,%9}, {%0,%1,%2,%3};"
        : "+f"(c[0]), "+f"(c[1]), "+f"(c[2]), "+f"(c[3])
        : "r"(a[0]), "r"(a[1]), "r"(a[2]), "r"(a[3]), "r"(b[0]), "r"(b[1]));
}
__device__ __forceinline__ float gelu_tanh(float v) {
    const float c = 0.7978845608028654f;
    float u = c * (v + 0.044715f * v * v * v);
    return 0.5f * v * (1.0f + tanhf(u));
}
__device__ __forceinline__ void split_h(float v, __half& h, __half& l) {
    h = __float2half_rn(v);
    l = __float2half_rn(v - __half2float(h));
}

// ------------------------- router / top-k / compact -------------------------
__global__ void router_scores_kernel(const float* __restrict__ x,
                                     const float* __restrict__ wr) {
    int gwarp = (blockIdx.x * blockDim.x + threadIdx.x) >> 5;
    int lane  = threadIdx.x & 31;
    if (gwarp >= B_ * L_) return;
    const float4* xr = (const float4*)(x + (size_t)gwarp * D_);
    const float4* w4 = (const float4*)wr;
    float acc = 0.f;
#pragma unroll
    for (int i = 0; i < D_ / 4 / 32; i++) {
        float4 a = xr[lane + i * 32];
        float4 b = w4[lane + i * 32];
        acc += a.x * b.x + a.y * b.y + a.z * b.z + a.w * b.w;
    }
#pragma unroll
    for (int off = 16; off; off >>= 1)
        acc += __shfl_xor_sync(0xffffffffu, acc, off);
    if (lane == 0) g_scores[gwarp] = acc;
}

__global__ void rank_kernel() {
    __shared__ float s[L_];
    int b = blockIdx.y;
    int t = threadIdx.x;
    const float* sc = g_scores + b * L_;
    for (int i = t; i < L_; i += 1024) s[i] = sc[i];
    __syncthreads();
    int   l  = blockIdx.x * 1024 + t;
    float sl = s[l];
    int rank = 0;
#pragma unroll 8
    for (int j = 0; j < L_; j++) {
        float sj = s[j];
        rank += (sj > sl) || (sj == sl && j < l);
    }
    g_flags[b * L_ + l] = (rank < KCAP_) ? 1 : 0;
}

__global__ void compact_kernel() {
    int b = blockIdx.x;
    int t = threadIdx.x;
    int tok0 = t * 4;
    int f[4], c = 0;
#pragma unroll
    for (int i = 0; i < 4; i++) {
        f[i] = g_flags[b * L_ + tok0 + i];
        c += f[i];
    }
    int lane = t & 31, w = t >> 5;
    int inc = c;
#pragma unroll
    for (int off = 1; off < 32; off <<= 1) {
        int y = __shfl_up_sync(0xffffffffu, inc, off);
        if (lane >= off) inc += y;
    }
    __shared__ int ws[32];
    if (lane == 31) ws[w] = inc;
    __syncthreads();
    if (w == 0) {
        int v = ws[lane];
#pragma unroll
        for (int off = 1; off < 32; off <<= 1) {
            int y = __shfl_up_sync(0xffffffffu, v, off);
            if (lane >= off) v += y;
        }
        ws[lane] = v;
    }
    __syncthreads();
    int selp = inc - c + (w ? ws[w - 1] : 0);
    int unsp = tok0 - selp;
#pragma unroll
    for (int i = 0; i < 4; i++) {
        if (f[i]) g_selidx[b * KCAP_ + selp++] = tok0 + i;
        else      g_unselidx[b * UNSEL_ + unsp++] = tok0 + i;
    }
}

// ------------------------- conversions -------------------------
__global__ void convert_split16_kernel(const float* __restrict__ src,
                                       __half* __restrict__ hi,
                                       __half* __restrict__ lo, int n4) {
    int i = blockIdx.x * blockDim.x + threadIdx.x;
    if (i >= n4) return;
    float4 v = ((const float4*)src)[i];
    __half h0, h1, h2, h3, l0, l1, l2, l3;
    split_h(v.x, h0, l0); split_h(v.y, h1, l1);
    split_h(v.z, h2, l2); split_h(v.w, h3, l3);
    __half2 ha = __halves2half2(h0, h1), hb = __halves2half2(h2, h3);
    __half2 la = __halves2half2(l0, l1), lb = __halves2half2(l2, l3);
    ((uint2*)hi)[i] = make_uint2(*(uint32_t*)&ha, *(uint32_t*)&hb);
    ((uint2*)lo)[i] = make_uint2(*(uint32_t*)&la, *(uint32_t*)&lb);
}

__global__ void gather_convert16_kernel(const float* __restrict__ x,
                                        const int* __restrict__ idx,
                                        __half* __restrict__ dst) {
    int i = blockIdx.x * blockDim.x + threadIdx.x;   // rows * 256
    int r = i >> 8;
    int c4 = i & 255;
    int srow = (r >> 11) * L_ + idx[r];
    float4 v = ((const float4*)(x + (size_t)srow * D_))[c4];
    __half2 a = __floats2half2_rn(v.x, v.y);
    __half2 b = __floats2half2_rn(v.z, v.w);
    ((uint2*)dst)[i] = make_uint2(*(uint32_t*)&a, *(uint32_t*)&b);
}

// ------------------------- HMMA GEMM (fp16, split-B 2-pass) -------------------------
// C[m,n] = sum_k A[m,k] * (Bh[n,k] + Bl[n,k])
// WHICH 0: bypass  A=g_xu16, B=wb,  C scatter->out (unselidx)  M=8192 N=1024 K=1024
// WHICH 1: ffn1    A=g_xg16, B=w1,  C=gelu->fp16->g_h16        M=8192 N=4096 K=1024
// WHICH 2: ffn2    A=g_h16,  B=w2,  C scatter->out (selidx)    M=8192 N=1024 K=4096
#define BKC     32
#define TILEB   8192               // 128 rows x 64B (swizzled)
#define STAGEB  (3 * TILEB)        // A, Bh, Bl
#define NSTAGE  4
#define SMEMB   (NSTAGE * STAGEB)  // 98304

// chunk swizzle: 16B chunk c of row r stored at c ^ ((r>>1)&3)
#define SWZ(r, c) (((uint32_t)(r)) * 64u + ((((uint32_t)(c)) ^ ((((uint32_t)(r)) >> 1) & 3u)) << 4))

template <int WHICH>
__global__ void __launch_bounds__(256, 2) gemm_mma(float* __restrict__ outp) {
    constexpr int K  = (WHICH == 2) ? DFF_ : D_;
    constexpr int NK = K / BKC;
    constexpr int NTN = (WHICH == 1) ? (DFF_ / 128) : (D_ / 128);
    constexpr int NTILES = 64 * NTN;   // M/128 = 64 always

    const __half* A  = (WHICH == 0) ? g_xu16 : (WHICH == 1) ? g_xg16 : g_h16;
    const __half* Bh = (WHICH == 0) ? g_wbh : (WHICH == 1) ? g_w1h : g_w2h;
    const __half* Bl = (WHICH == 0) ? g_wbl : (WHICH == 1) ? g_w1l : g_w2l;

    extern __shared__ char smem[];
    const uint32_t sbase = smem_u32(smem);

    const int tid  = threadIdx.x;
    const int lane = tid & 31;
    const int wid  = tid >> 5;

    // cp.async per-thread layout: row pr, chunk pair pc{,+1}
    const int pr = tid >> 1;
    const int pc = (tid & 1) * 2;
    const uint32_t d0 = SWZ(pr, pc);
    const uint32_t d1 = SWZ(pr, pc + 1);

    // warp tiling: 2(m) x 4(n), warp tile 64x32
    const uint32_t wrow0 = (wid & 1) * 64;
    const uint32_t wcol0 = (wid >> 1) * 32;
    const uint32_t aRow = wrow0 + (lane & 15);
    const uint32_t aK   = (lane >> 4);
    const uint32_t bRow = wcol0 + ((lane >> 4) << 3) + (lane & 7);
    const uint32_t bK   = (lane >> 3) & 1;

    // precompute ldmatrix row bases + swizzle selectors
    uint32_t aBase[4], aSwz[4];
#pragma unroll
    for (int i = 0; i < 4; i++) {
        uint32_t r = aRow + i * 16;
        aBase[i] = r * 64u;
        aSwz[i]  = (r >> 1) & 3u;
    }
    uint32_t bBase[2], bSwz[2];
#pragma unroll
    for (int jp = 0; jp < 2; jp++) {
        uint32_t r = bRow + jp * 16;
        bBase[jp] = r * 64u;
        bSwz[jp]  = (r >> 1) & 3u;
    }

    const int t4  = lane >> 2;
    const int tm2 = (lane & 3) * 2;

    for (int tile = blockIdx.x; tile < NTILES; tile += gridDim.x) {
        const int bm = tile / NTN;
        const int bn = tile % NTN;

        const __half* srcA  = A  + (size_t)(bm * 128 + pr) * K + pc * 8;
        const __half* srcBh = Bh + (size_t)(bn * 128 + pr) * K + pc * 8;
        const __half* srcBl = Bl + (size_t)(bn * 128 + pr) * K + pc * 8;

#define LOAD_STAGE(ks, st) do {                                          \
        uint32_t b0 = sbase + (st) * STAGEB;                             \
        int ko = (ks) * BKC;                                             \
        cp16(b0 + d0,              srcA  + ko);                          \
        cp16(b0 + d1,              srcA  + ko + 8);                      \
        cp16(b0 + TILEB + d0,      srcBh + ko);                          \
        cp16(b0 + TILEB + d1,      srcBh + ko + 8);                      \
        cp16(b0 + 2 * TILEB + d0,  srcBl + ko);                          \
        cp16(b0 + 2 * TILEB + d1,  srcBl + ko + 8);                      \
        CP_COMMIT();                                                     \
    } while (0)

        float acc[4][4][4];
#pragma unroll
        for (int i = 0; i < 4; i++)
#pragma unroll
            for (int j = 0; j < 4; j++)
#pragma unroll
                for (int q = 0; q < 4; q++) acc[i][j][q] = 0.f;

        LOAD_STAGE(0, 0);
        LOAD_STAGE(1, 1);
        LOAD_STAGE(2, 2);

        int st = 0;
        for (int ks = 0; ks < NK; ks++) {
            CP_WAIT2();
            __syncthreads();

            // issue load for ks+3 into stage freed at ks-1
            if (ks + 3 < NK) {
                int st3 = st + 3; if (st3 >= NSTAGE) st3 -= NSTAGE;
                LOAD_STAGE(ks + 3, st3);
            } else {
                CP_COMMIT();
            }

            const uint32_t base = sbase + st * STAGEB;
#pragma unroll
            for (int s = 0; s < 2; s++) {
                uint32_t a[4][4];
                uint32_t b[4][2];
#pragma unroll
                for (int i = 0; i < 4; i++) {
                    uint32_t c = 2 * s + aK;
                    ldx4(a[i], base + aBase[i] + ((c ^ aSwz[i]) << 4));
                }
                // pass 1: A * Bh
#pragma unroll
                for (int jp = 0; jp < 2; jp++) {
                    uint32_t r[4];
                    uint32_t c = 2 * s + bK;
                    ldx4(r, base + TILEB + bBase[jp] + ((c ^ bSwz[jp]) << 4));
                    b[2 * jp][0] = r[0]; b[2 * jp][1] = r[1];
                    b[2 * jp + 1][0] = r[2]; b[2 * jp + 1][1] = r[3];
                }
#pragma unroll
                for (int i = 0; i < 4; i++)
#pragma unroll
                    for (int j = 0; j < 4; j++) mma16816(acc[i][j], a[i], b[j]);
                // pass 2: A * Bl
#pragma unroll
                for (int jp = 0; jp < 2; jp++) {
                    uint32_t r[4];
                    uint32_t c = 2 * s + bK;
                    ldx4(r, base + 2 * TILEB + bBase[jp] + ((c ^ bSwz[jp]) << 4));
                    b[2 * jp][0] = r[0]; b[2 * jp][1] = r[1];
                    b[2 * jp + 1][0] = r[2]; b[2 * jp + 1][1] = r[3];
                }
#pragma unroll
                for (int i = 0; i < 4; i++)
#pragma unroll
                    for (int j = 0; j < 4; j++) mma16816(acc[i][j], a[i], b[j]);
            }
            if (++st == NSTAGE) st = 0;
        }

        // ---- epilogue ----
#pragma unroll
        for (int i = 0; i < 4; i++) {
            int r0 = bm * 128 + (int)wrow0 + i * 16 + t4;
            int r1 = r0 + 8;
            int or0, or1;
            if (WHICH == 0)      { or0 = (r0 >> 11) * L_ + g_unselidx[r0]; or1 = (r1 >> 11) * L_ + g_unselidx[r1]; }
            else if (WHICH == 2) { or0 = (r0 >> 11) * L_ + g_selidx[r0];   or1 = (r1 >> 11) * L_ + g_selidx[r1];   }
            else                 { or0 = r0; or1 = r1; }
#pragma unroll
            for (int j = 0; j < 4; j++) {
                int col = bn * 128 + (int)wcol0 + j * 8 + tm2;
                if (WHICH == 1) {
                    __half2 p0 = __floats2half2_rn(gelu_tanh(acc[i][j][0]), gelu_tanh(acc[i][j][1]));
                    __half2 p1 = __floats2half2_rn(gelu_tanh(acc[i][j][2]), gelu_tanh(acc[i][j][3]));
                    *(uint32_t*)(g_h16 + (size_t)r0 * DFF_ + col) = *(uint32_t*)&p0;
                    *(uint32_t*)(g_h16 + (size_t)r1 * DFF_ + col) = *(uint32_t*)&p1;
                } else {
                    *(float2*)(outp + (size_t)or0 * D_ + col) = make_float2(acc[i][j][0], acc[i][j][1]);
                    *(float2*)(outp + (size_t)or1 * D_ + col) = make_float2(acc[i][j][2], acc[i][j][3]);
                }
            }
        }
#undef LOAD_STAGE
    }
}

// ------------------------- launch -------------------------
extern "C" void kernel_launch(void* const* d_in, const int* in_sizes, int n_in,
                              void* d_out, int out_size) {
    const float* x  = (const float*)d_in[0];
    const float* wr = (const float*)d_in[1];
    const float* wb = (const float*)d_in[2];
    const float* w1 = (const float*)d_in[3];
    const float* w2 = (const float*)d_in[4];
    float* out = (float*)d_out;

    cudaFuncSetAttribute(gemm_mma<0>, cudaFuncAttributeMaxDynamicSharedMemorySize, SMEMB);
    cudaFuncSetAttribute(gemm_mma<1>, cudaFuncAttributeMaxDynamicSharedMemorySize, SMEMB);
    cudaFuncSetAttribute(gemm_mma<2>, cudaFuncAttributeMaxDynamicSharedMemorySize, SMEMB);

    router_scores_kernel<<<(B_ * L_) / 8, 256>>>(x, wr);
    rank_kernel<<<dim3(L_ / 1024, B_), 1024>>>();
    compact_kernel<<<B_, 1024>>>();

    __half *p_wbh, *p_wbl, *p_w1h, *p_w1l, *p_w2h, *p_w2l, *p_xg, *p_xu;
    int *p_sel, *p_unsel;
    cudaGetSymbolAddress((void**)&p_wbh, g_wbh);
    cudaGetSymbolAddress((void**)&p_wbl, g_wbl);
    cudaGetSymbolAddress((void**)&p_w1h, g_w1h);
    cudaGetSymbolAddress((void**)&p_w1l, g_w1l);
    cudaGetSymbolAddress((void**)&p_w2h, g_w2h);
    cudaGetSymbolAddress((void**)&p_w2l, g_w2l);
    cudaGetSymbolAddress((void**)&p_xg,  g_xg16);
    cudaGetSymbolAddress((void**)&p_xu,  g_xu16);
    cudaGetSymbolAddress((void**)&p_sel, g_selidx);
    cudaGetSymbolAddress((void**)&p_unsel, g_unselidx);

    convert_split16_kernel<<<(D_ * D_ / 4) / 256, 256>>>(wb, p_wbh, p_wbl, D_ * D_ / 4);
    convert_split16_kernel<<<(DFF_ * D_ / 4) / 256, 256>>>(w1, p_w1h, p_w1l, DFF_ * D_ / 4);
    convert_split16_kernel<<<(D_ * DFF_ / 4) / 256, 256>>>(w2, p_w2h, p_w2l, D_ * DFF_ / 4);
    gather_convert16_kernel<<<(B_ * KCAP_  * 256) / 256, 256>>>(x, p_sel,   p_xg);
    gather_convert16_kernel<<<(B_ * UNSEL_ * 256) / 256, 256>>>(x, p_unsel, p_xu);

    // persistent GEMMs: 2 CTAs/SM x 148 SMs
    gemm_mma<0><<<296, 256, SMEMB>>>(out);
    gemm_mma<1><<<296, 256, SMEMB>>>(out);
    gemm_mma<2><<<296, 256, SMEMB>>>(out);
}

// round 5
// speedup vs baseline: 4.7560x; 1.5445x over previous
#include <cuda_runtime.h>
#include <cuda_fp16.h>
#include <math.h>
#include <stdint.h>

#define B_    4
#define L_    4096
#define D_    1024
#define DFF_  4096
#define KCAP_ 2048
#define UNSEL_ 2048

// ------------------------- scratch globals -------------------------
__device__ float g_scores[B_ * L_];
__device__ int   g_flags[B_ * L_];
__device__ int   g_selidx[B_ * KCAP_];
__device__ int   g_unselidx[B_ * UNSEL_];

__device__ __align__(16) __half g_xg16[(size_t)B_ * KCAP_ * D_];
__device__ __align__(16) __half g_xu16[(size_t)B_ * UNSEL_ * D_];
__device__ __align__(16) __half g_wb16[(size_t)D_ * D_];
__device__ __align__(16) __half g_w116[(size_t)DFF_ * D_];
__device__ __align__(16) __half g_w216[(size_t)D_ * DFF_];
__device__ __align__(16) __half g_h16 [(size_t)B_ * KCAP_ * DFF_];

// ------------------------- helpers -------------------------
__device__ __forceinline__ uint32_t smem_u32(const void* p) {
    uint32_t a;
    asm("{ .reg .u64 t; cvta.to.shared.u64 t, %1; cvt.u32.u64 %0, t; }"
        : "=r"(a) : "l"(p));
    return a;
}
__device__ __forceinline__ void cp16(uint32_t dst, const void* src) {
    asm volatile("cp.async.cg.shared.global [%0], [%1], 16;" :: "r"(dst), "l"(src));
}
#define CP_COMMIT() asm volatile("cp.async.commit_group;" ::: "memory")
#define CP_WAIT3()  asm volatile("cp.async.wait_group 3;" ::: "memory")

__device__ __forceinline__ void ldx4(uint32_t r[4], uint32_t addr) {
    asm volatile("ldmatrix.sync.aligned.m8n8.x4.shared.b16 {%0,%1,%2,%3}, [%4];"
                 : "=r"(r[0]), "=r"(r[1]), "=r"(r[2]), "=r"(r[3]) : "r"(addr));
}
__device__ __forceinline__ void mma16816(float c[4], const uint32_t a[4], const uint32_t b[2]) {
    asm volatile(
        "mma.sync.aligned.m16n8k16.row.col.f32.f16.f16.f32 "
        "{%0,%1,%2,%3}, {%4,%5,%6,%7}, {%8,%9}, {%0,%1,%2,%3};"
        : "+f"(c[0]), "+f"(c[1]), "+f"(c[2]), "+f"(c[3])
        : "r"(a[0]), "r"(a[1]), "r"(a[2]), "r"(a[3]), "r"(b[0]), "r"(b[1]));
}
__device__ __forceinline__ float gelu_tanh(float v) {
    const float c = 0.7978845608028654f;
    float u = c * (v + 0.044715f * v * v * v);
    return 0.5f * v * (1.0f + tanhf(u));
}

// ------------------------- router / top-k / compact -------------------------
__global__ void router_scores_kernel(const float* __restrict__ x,
                                     const float* __restrict__ wr) {
    int gwarp = (blockIdx.x * blockDim.x + threadIdx.x) >> 5;
    int lane  = threadIdx.x & 31;
    if (gwarp >= B_ * L_) return;
    const float4* xr = (const float4*)(x + (size_t)gwarp * D_);
    const float4* w4 = (const float4*)wr;
    float acc = 0.f;
#pragma unroll
    for (int i = 0; i < D_ / 4 / 32; i++) {
        float4 a = xr[lane + i * 32];
        float4 b = w4[lane + i * 32];
        acc += a.x * b.x + a.y * b.y + a.z * b.z + a.w * b.w;
    }
#pragma unroll
    for (int off = 16; off; off >>= 1)
        acc += __shfl_xor_sync(0xffffffffu, acc, off);
    if (lane == 0) g_scores[gwarp] = acc;
}

__global__ void rank_kernel() {
    __shared__ float s[L_];
    int b = blockIdx.y;
    int t = threadIdx.x;
    const float* sc = g_scores + b * L_;
    for (int i = t; i < L_; i += 1024) s[i] = sc[i];
    __syncthreads();
    int   l  = blockIdx.x * 1024 + t;
    float sl = s[l];
    int rank = 0;
#pragma unroll 8
    for (int j = 0; j < L_; j++) {
        float sj = s[j];
        rank += (sj > sl) || (sj == sl && j < l);
    }
    g_flags[b * L_ + l] = (rank < KCAP_) ? 1 : 0;
}

__global__ void compact_kernel() {
    int b = blockIdx.x;
    int t = threadIdx.x;
    int tok0 = t * 4;
    int f[4], c = 0;
#pragma unroll
    for (int i = 0; i < 4; i++) {
        f[i] = g_flags[b * L_ + tok0 + i];
        c += f[i];
    }
    int lane = t & 31, w = t >> 5;
    int inc = c;
#pragma unroll
    for (int off = 1; off < 32; off <<= 1) {
        int y = __shfl_up_sync(0xffffffffu, inc, off);
        if (lane >= off) inc += y;
    }
    __shared__ int ws[32];
    if (lane == 31) ws[w] = inc;
    __syncthreads();
    if (w == 0) {
        int v = ws[lane];
#pragma unroll
        for (int off = 1; off < 32; off <<= 1) {
            int y = __shfl_up_sync(0xffffffffu, v, off);
            if (lane >= off) v += y;
        }
        ws[lane] = v;
    }
    __syncthreads();
    int selp = inc - c + (w ? ws[w - 1] : 0);
    int unsp = tok0 - selp;
#pragma unroll
    for (int i = 0; i < 4; i++) {
        if (f[i]) g_selidx[b * KCAP_ + selp++] = tok0 + i;
        else      g_unselidx[b * UNSEL_ + unsp++] = tok0 + i;
    }
}

// ------------------------- conversions -------------------------
__global__ void convert16_kernel(const float* __restrict__ src,
                                 __half* __restrict__ dst, int n4) {
    int i = blockIdx.x * blockDim.x + threadIdx.x;
    if (i >= n4) return;
    float4 v = ((const float4*)src)[i];
    __half2 a = __floats2half2_rn(v.x, v.y);
    __half2 b = __floats2half2_rn(v.z, v.w);
    ((uint2*)dst)[i] = make_uint2(*(uint32_t*)&a, *(uint32_t*)&b);
}

__global__ void gather_convert16_kernel(const float* __restrict__ x,
                                        const int* __restrict__ idx,
                                        __half* __restrict__ dst) {
    int i = blockIdx.x * blockDim.x + threadIdx.x;   // rows * 256
    int r = i >> 8;
    int c4 = i & 255;
    int srow = (r >> 11) * L_ + idx[r];
    float4 v = ((const float4*)(x + (size_t)srow * D_))[c4];
    __half2 a = __floats2half2_rn(v.x, v.y);
    __half2 b = __floats2half2_rn(v.z, v.w);
    ((uint2*)dst)[i] = make_uint2(*(uint32_t*)&a, *(uint32_t*)&b);
}

// ------------------------- HMMA GEMM (fp16 single-pass) -------------------------
// C[m,n] = sum_k A[m,k] * B[n,k]
// WHICH 0: bypass  A=g_xu16, B=wb,  C scatter->out (unselidx)  M=8192 N=1024 K=1024
// WHICH 1: ffn1    A=g_xg16, B=w1,  C=gelu->fp16->g_h16        M=8192 N=4096 K=1024
// WHICH 2: ffn2    A=g_h16,  B=w2,  C scatter->out (selidx)    M=8192 N=1024 K=4096
#define BKC     32
#define TILEB   8192               // 128 rows x 64B (swizzled)
#define STAGEB  (2 * TILEB)        // A, B
#define NSTAGE  5
#define SMEMB   (NSTAGE * STAGEB)  // 81920

// chunk swizzle: 16B chunk c of row r stored at c ^ ((r>>1)&3)
#define SWZ(r, c) (((uint32_t)(r)) * 64u + ((((uint32_t)(c)) ^ ((((uint32_t)(r)) >> 1) & 3u)) << 4))

template <int WHICH>
__global__ void __launch_bounds__(256, 2) gemm_mma(float* __restrict__ outp) {
    constexpr int K  = (WHICH == 2) ? DFF_ : D_;
    constexpr int NK = K / BKC;
    constexpr int NTN = (WHICH == 1) ? (DFF_ / 128) : (D_ / 128);
    constexpr int NTILES = 64 * NTN;   // M/128 = 64 always

    const __half* A = (WHICH == 0) ? g_xu16 : (WHICH == 1) ? g_xg16 : g_h16;
    const __half* B = (WHICH == 0) ? g_wb16 : (WHICH == 1) ? g_w116 : g_w216;

    extern __shared__ char smem[];
    const uint32_t sbase = smem_u32(smem);

    const int tid  = threadIdx.x;
    const int lane = tid & 31;
    const int wid  = tid >> 5;

    // cp.async per-thread layout: row pr, chunk pair pc{,+1}
    const int pr = tid >> 1;
    const int pc = (tid & 1) * 2;
    const uint32_t d0 = SWZ(pr, pc);
    const uint32_t d1 = SWZ(pr, pc + 1);

    // warp tiling: 2(m) x 4(n), warp tile 64x32
    const uint32_t wrow0 = (wid & 1) * 64;
    const uint32_t wcol0 = (wid >> 1) * 32;
    const uint32_t aRow = wrow0 + (lane & 15);
    const uint32_t aK   = (lane >> 4);
    const uint32_t bRow = wcol0 + ((lane >> 4) << 3) + (lane & 7);
    const uint32_t bK   = (lane >> 3) & 1;

    uint32_t aBase[4], aSwz[4];
#pragma unroll
    for (int i = 0; i < 4; i++) {
        uint32_t r = aRow + i * 16;
        aBase[i] = r * 64u;
        aSwz[i]  = (r >> 1) & 3u;
    }
    uint32_t bBase[2], bSwz[2];
#pragma unroll
    for (int jp = 0; jp < 2; jp++) {
        uint32_t r = bRow + jp * 16;
        bBase[jp] = r * 64u;
        bSwz[jp]  = (r >> 1) & 3u;
    }

    const int t4  = lane >> 2;
    const int tm2 = (lane & 3) * 2;

    for (int tile = blockIdx.x; tile < NTILES; tile += gridDim.x) {
        const int bm = tile / NTN;
        const int bn = tile % NTN;

        const __half* srcA = A + (size_t)(bm * 128 + pr) * K + pc * 8;
        const __half* srcB = B + (size_t)(bn * 128 + pr) * K + pc * 8;

#define LOAD_STAGE(ks, st) do {                                          \
        uint32_t b0 = sbase + (st) * STAGEB;                             \
        int ko = (ks) * BKC;                                             \
        cp16(b0 + d0,         srcA + ko);                                \
        cp16(b0 + d1,         srcA + ko + 8);                            \
        cp16(b0 + TILEB + d0, srcB + ko);                                \
        cp16(b0 + TILEB + d1, srcB + ko + 8);                            \
        CP_COMMIT();                                                     \
    } while (0)

        float acc[4][4][4];
#pragma unroll
        for (int i = 0; i < 4; i++)
#pragma unroll
            for (int j = 0; j < 4; j++)
#pragma unroll
                for (int q = 0; q < 4; q++) acc[i][j][q] = 0.f;

        LOAD_STAGE(0, 0);
        LOAD_STAGE(1, 1);
        LOAD_STAGE(2, 2);
        LOAD_STAGE(3, 3);

        int st = 0;
        for (int ks = 0; ks < NK; ks++) {
            CP_WAIT3();
            __syncthreads();

            // issue load for ks+4 into the stage freed at ks-1
            if (ks + 4 < NK) {
                int st4 = st + 4; if (st4 >= NSTAGE) st4 -= NSTAGE;
                LOAD_STAGE(ks + 4, st4);
            } else {
                CP_COMMIT();
            }

            const uint32_t base = sbase + st * STAGEB;
#pragma unroll
            for (int s = 0; s < 2; s++) {
                uint32_t a[4][4];
                uint32_t b[4][2];
#pragma unroll
                for (int i = 0; i < 4; i++) {
                    uint32_t c = 2 * s + aK;
                    ldx4(a[i], base + aBase[i] + ((c ^ aSwz[i]) << 4));
                }
#pragma unroll
                for (int jp = 0; jp < 2; jp++) {
                    uint32_t r[4];
                    uint32_t c = 2 * s + bK;
                    ldx4(r, base + TILEB + bBase[jp] + ((c ^ bSwz[jp]) << 4));
                    b[2 * jp][0] = r[0]; b[2 * jp][1] = r[1];
                    b[2 * jp + 1][0] = r[2]; b[2 * jp + 1][1] = r[3];
                }
#pragma unroll
                for (int i = 0; i < 4; i++)
#pragma unroll
                    for (int j = 0; j < 4; j++) mma16816(acc[i][j], a[i], b[j]);
            }
            if (++st == NSTAGE) st = 0;
        }

        // ---- epilogue ----
#pragma unroll
        for (int i = 0; i < 4; i++) {
            int r0 = bm * 128 + (int)wrow0 + i * 16 + t4;
            int r1 = r0 + 8;
            int or0, or1;
            if (WHICH == 0)      { or0 = (r0 >> 11) * L_ + g_unselidx[r0]; or1 = (r1 >> 11) * L_ + g_unselidx[r1]; }
            else if (WHICH == 2) { or0 = (r0 >> 11) * L_ + g_selidx[r0];   or1 = (r1 >> 11) * L_ + g_selidx[r1];   }
            else                 { or0 = r0; or1 = r1; }
#pragma unroll
            for (int j = 0; j < 4; j++) {
                int col = bn * 128 + (int)wcol0 + j * 8 + tm2;
                if (WHICH == 1) {
                    __half2 p0 = __floats2half2_rn(gelu_tanh(acc[i][j][0]), gelu_tanh(acc[i][j][1]));
                    __half2 p1 = __floats2half2_rn(gelu_tanh(acc[i][j][2]), gelu_tanh(acc[i][j][3]));
                    *(uint32_t*)(g_h16 + (size_t)r0 * DFF_ + col) = *(uint32_t*)&p0;
                    *(uint32_t*)(g_h16 + (size_t)r1 * DFF_ + col) = *(uint32_t*)&p1;
                } else {
                    *(float2*)(outp + (size_t)or0 * D_ + col) = make_float2(acc[i][j][0], acc[i][j][1]);
                    *(float2*)(outp + (size_t)or1 * D_ + col) = make_float2(acc[i][j][2], acc[i][j][3]);
                }
            }
        }
#undef LOAD_STAGE
    }
}

// ------------------------- launch -------------------------
extern "C" void kernel_launch(void* const* d_in, const int* in_sizes, int n_in,
                              void* d_out, int out_size) {
    const float* x  = (const float*)d_in[0];
    const float* wr = (const float*)d_in[1];
    const float* wb = (const float*)d_in[2];
    const float* w1 = (const float*)d_in[3];
    const float* w2 = (const float*)d_in[4];
    float* out = (float*)d_out;

    cudaFuncSetAttribute(gemm_mma<0>, cudaFuncAttributeMaxDynamicSharedMemorySize, SMEMB);
    cudaFuncSetAttribute(gemm_mma<1>, cudaFuncAttributeMaxDynamicSharedMemorySize, SMEMB);
    cudaFuncSetAttribute(gemm_mma<2>, cudaFuncAttributeMaxDynamicSharedMemorySize, SMEMB);

    router_scores_kernel<<<(B_ * L_) / 8, 256>>>(x, wr);
    rank_kernel<<<dim3(L_ / 1024, B_), 1024>>>();
    compact_kernel<<<B_, 1024>>>();

    __half *p_wb, *p_w1, *p_w2, *p_xg, *p_xu;
    int *p_sel, *p_unsel;
    cudaGetSymbolAddress((void**)&p_wb, g_wb16);
    cudaGetSymbolAddress((void**)&p_w1, g_w116);
    cudaGetSymbolAddress((void**)&p_w2, g_w216);
    cudaGetSymbolAddress((void**)&p_xg, g_xg16);
    cudaGetSymbolAddress((void**)&p_xu, g_xu16);
    cudaGetSymbolAddress((void**)&p_sel, g_selidx);
    cudaGetSymbolAddress((void**)&p_unsel, g_unselidx);

    convert16_kernel<<<(D_ * D_ / 4) / 256, 256>>>(wb, p_wb, D_ * D_ / 4);
    convert16_kernel<<<(DFF_ * D_ / 4) / 256, 256>>>(w1, p_w1, DFF_ * D_ / 4);
    convert16_kernel<<<(D_ * DFF_ / 4) / 256, 256>>>(w2, p_w2, D_ * DFF_ / 4);
    gather_convert16_kernel<<<(B_ * KCAP_  * 256) / 256, 256>>>(x, p_sel,   p_xg);
    gather_convert16_kernel<<<(B_ * UNSEL_ * 256) / 256, 256>>>(x, p_unsel, p_xu);

    // persistent GEMMs: 2 CTAs/SM x 148 SMs
    gemm_mma<0><<<296, 256, SMEMB>>>(out);
    gemm_mma<1><<<296, 256, SMEMB>>>(out);
    gemm_mma<2><<<296, 256, SMEMB>>>(out);
}